// round 1
// baseline (speedup 1.0000x reference)
#include <cuda_runtime.h>
#include <math.h>

// OnlineNeuron: T=4 two-compartment SNN recurrence, elementwise over [B,C,H,W].
//   a1 = sigmoid(alpha_1)-0.5 ; b1 = sigmoid(beta_1)-0.5
//   a2 = sigmoid(alpha_2)+0.5 ; b2 = sigmoid(beta_2)+0.5
//   v_d = a1*v_d + b1*v_s + x_t
//   v_s = a2*v_s + b2*v_d
//   out = (v_s - 1 >= 0) ? 1 : 0 ;  v_s -= out
// x is [T*B, C, H, W] with T=4 (timestep-major). Each thread owns one float4
// of the spatial slab across all 4 timesteps. Pure HBM-streaming.

#define T_STEPS 4

__device__ __forceinline__ float sigmoidf_(float v) {
    return 1.0f / (1.0f + expf(-v));
}

__global__ __launch_bounds__(256)
void online_neuron_kernel(const float4* __restrict__ x,
                          const float* __restrict__ alpha1,
                          const float* __restrict__ beta1,
                          const float* __restrict__ alpha2,
                          const float* __restrict__ beta2,
                          float4* __restrict__ out,
                          int n4)   // float4 count per timestep slab
{
    int i = blockIdx.x * blockDim.x + threadIdx.x;
    if (i >= n4) return;

    const float a1 = sigmoidf_(__ldg(alpha1)) - 0.5f;
    const float b1 = sigmoidf_(__ldg(beta1))  - 0.5f;
    const float a2 = sigmoidf_(__ldg(alpha2)) + 0.5f;
    const float b2 = sigmoidf_(__ldg(beta2))  + 0.5f;

    float4 vd = make_float4(0.f, 0.f, 0.f, 0.f);
    float4 vs = make_float4(0.5f, 0.5f, 0.5f, 0.5f);

    const long long stride = (long long)n4;   // float4 units between timesteps

    #pragma unroll
    for (int t = 0; t < T_STEPS; t++) {
        float4 xt = __ldcs(&x[(long long)t * stride + i]);

        vd.x = a1 * vd.x + b1 * vs.x + xt.x;
        vd.y = a1 * vd.y + b1 * vs.y + xt.y;
        vd.z = a1 * vd.z + b1 * vs.z + xt.z;
        vd.w = a1 * vd.w + b1 * vs.w + xt.w;

        vs.x = a2 * vs.x + b2 * vd.x;
        vs.y = a2 * vs.y + b2 * vd.y;
        vs.z = a2 * vs.z + b2 * vd.z;
        vs.w = a2 * vs.w + b2 * vd.w;

        float4 o;
        o.x = (vs.x - 1.0f >= 0.0f) ? 1.0f : 0.0f;
        o.y = (vs.y - 1.0f >= 0.0f) ? 1.0f : 0.0f;
        o.z = (vs.z - 1.0f >= 0.0f) ? 1.0f : 0.0f;
        o.w = (vs.w - 1.0f >= 0.0f) ? 1.0f : 0.0f;

        vs.x -= o.x;  vs.y -= o.y;  vs.z -= o.z;  vs.w -= o.w;

        __stcs(&out[(long long)t * stride + i], o);
    }
}

extern "C" void kernel_launch(void* const* d_in, const int* in_sizes, int n_in,
                              void* d_out, int out_size)
{
    const float* x      = (const float*)d_in[0];
    const float* alpha1 = (const float*)d_in[1];
    const float* beta1  = (const float*)d_in[2];
    const float* alpha2 = (const float*)d_in[3];
    const float* beta2  = (const float*)d_in[4];
    float* out = (float*)d_out;

    const int n_total = in_sizes[0];          // 512*128*32*32
    const int n_slab  = n_total / T_STEPS;    // elements per timestep slab
    const int n4      = n_slab / 4;           // float4 per slab

    const int block = 256;
    const int grid  = (n4 + block - 1) / block;

    online_neuron_kernel<<<grid, block>>>(
        (const float4*)x, alpha1, beta1, alpha2, beta2, (float4*)out, n4);
}

// round 2
// speedup vs baseline: 1.0051x; 1.0051x over previous
#include <cuda_runtime.h>
#include <math.h>

// OnlineNeuron: T=4 two-compartment SNN recurrence, elementwise over [B,C,H,W].
// Pure HBM-streaming (512 MB total traffic). Round-2 change: front-batch all
// four timestep LDG.128s (loads are independent of the recurrence) to raise
// per-thread MLP from 1 to 4, then compute, then store all four outputs.

#define T_STEPS 4

__device__ __forceinline__ float sigmoidf_(float v) {
    return 1.0f / (1.0f + expf(-v));
}

__global__ __launch_bounds__(256)
void online_neuron_kernel(const float4* __restrict__ x,
                          const float* __restrict__ alpha1,
                          const float* __restrict__ beta1,
                          const float* __restrict__ alpha2,
                          const float* __restrict__ beta2,
                          float4* __restrict__ out,
                          int n4)   // float4 count per timestep slab
{
    int i = blockIdx.x * blockDim.x + threadIdx.x;
    if (i >= n4) return;

    const long long stride = (long long)n4;   // float4 units between timesteps

    // ---- Front-batched loads: 4 independent LDG.128 in flight (MLP=4) ----
    float4 xt[T_STEPS];
    #pragma unroll
    for (int t = 0; t < T_STEPS; t++)
        xt[t] = __ldcs(&x[(long long)t * stride + i]);

    const float a1 = sigmoidf_(__ldg(alpha1)) - 0.5f;
    const float b1 = sigmoidf_(__ldg(beta1))  - 0.5f;
    const float a2 = sigmoidf_(__ldg(alpha2)) + 0.5f;
    const float b2 = sigmoidf_(__ldg(beta2))  + 0.5f;

    float4 vd = make_float4(0.f, 0.f, 0.f, 0.f);
    float4 vs = make_float4(0.5f, 0.5f, 0.5f, 0.5f);

    float4 o[T_STEPS];

    #pragma unroll
    for (int t = 0; t < T_STEPS; t++) {
        vd.x = a1 * vd.x + b1 * vs.x + xt[t].x;
        vd.y = a1 * vd.y + b1 * vs.y + xt[t].y;
        vd.z = a1 * vd.z + b1 * vs.z + xt[t].z;
        vd.w = a1 * vd.w + b1 * vs.w + xt[t].w;

        vs.x = a2 * vs.x + b2 * vd.x;
        vs.y = a2 * vs.y + b2 * vd.y;
        vs.z = a2 * vs.z + b2 * vd.z;
        vs.w = a2 * vs.w + b2 * vd.w;

        o[t].x = (vs.x - 1.0f >= 0.0f) ? 1.0f : 0.0f;
        o[t].y = (vs.y - 1.0f >= 0.0f) ? 1.0f : 0.0f;
        o[t].z = (vs.z - 1.0f >= 0.0f) ? 1.0f : 0.0f;
        o[t].w = (vs.w - 1.0f >= 0.0f) ? 1.0f : 0.0f;

        vs.x -= o[t].x;  vs.y -= o[t].y;  vs.z -= o[t].z;  vs.w -= o[t].w;
    }

    // ---- Back-batched stores ----
    #pragma unroll
    for (int t = 0; t < T_STEPS; t++)
        __stcs(&out[(long long)t * stride + i], o[t]);
}

extern "C" void kernel_launch(void* const* d_in, const int* in_sizes, int n_in,
                              void* d_out, int out_size)
{
    const float* x      = (const float*)d_in[0];
    const float* alpha1 = (const float*)d_in[1];
    const float* beta1  = (const float*)d_in[2];
    const float* alpha2 = (const float*)d_in[3];
    const float* beta2  = (const float*)d_in[4];
    float* out = (float*)d_out;

    const int n_total = in_sizes[0];          // 512*128*32*32
    const int n_slab  = n_total / T_STEPS;    // elements per timestep slab
    const int n4      = n_slab / 4;           // float4 per slab

    const int block = 256;
    const int grid  = (n4 + block - 1) / block;

    online_neuron_kernel<<<grid, block>>>(
        (const float4*)x, alpha1, beta1, alpha2, beta2, (float4*)out, n4);
}

// round 3
// speedup vs baseline: 1.0059x; 1.0008x over previous
#include <cuda_runtime.h>
#include <math.h>

// OnlineNeuron: T=4 two-compartment SNN recurrence, elementwise, f32.
// Pure HBM-streaming: 256 MB read + 256 MB write, irreducible.
// Round-3: 2 float4 tiles per thread (block-strided), all 8 LDG.128 front-
// batched -> per-thread MLP=8; 8 STG.128 back-batched. Grid halves to 8192.

#define T_STEPS 4

__device__ __forceinline__ float sigmoidf_(float v) {
    return 1.0f / (1.0f + expf(-v));
}

__device__ __forceinline__ void step4(float4& vd, float4& vs, const float4 xt,
                                      float a1, float b1, float a2, float b2,
                                      float4& o)
{
    vd.x = a1 * vd.x + b1 * vs.x + xt.x;
    vd.y = a1 * vd.y + b1 * vs.y + xt.y;
    vd.z = a1 * vd.z + b1 * vs.z + xt.z;
    vd.w = a1 * vd.w + b1 * vs.w + xt.w;

    vs.x = a2 * vs.x + b2 * vd.x;
    vs.y = a2 * vs.y + b2 * vd.y;
    vs.z = a2 * vs.z + b2 * vd.z;
    vs.w = a2 * vs.w + b2 * vd.w;

    o.x = (vs.x >= 1.0f) ? 1.0f : 0.0f;
    o.y = (vs.y >= 1.0f) ? 1.0f : 0.0f;
    o.z = (vs.z >= 1.0f) ? 1.0f : 0.0f;
    o.w = (vs.w >= 1.0f) ? 1.0f : 0.0f;

    vs.x -= o.x;  vs.y -= o.y;  vs.z -= o.z;  vs.w -= o.w;
}

__global__ __launch_bounds__(256, 4)
void online_neuron_kernel(const float4* __restrict__ x,
                          const float* __restrict__ alpha1,
                          const float* __restrict__ beta1,
                          const float* __restrict__ alpha2,
                          const float* __restrict__ beta2,
                          float4* __restrict__ out,
                          int n4)   // float4 count per timestep slab
{
    // Each block owns a 512-float4 tile; each thread two block-strided float4s.
    const int base = blockIdx.x * 512 + threadIdx.x;
    const int ia = base;          // lane-dense across warp
    const int ib = base + 256;    // lane-dense across warp

    const long long stride = (long long)n4;   // float4 units between timesteps

    // ---- Front-batched loads: 8 independent LDG.128 in flight ----
    float4 xa[T_STEPS], xb[T_STEPS];
    #pragma unroll
    for (int t = 0; t < T_STEPS; t++) {
        xa[t] = __ldcs(&x[(long long)t * stride + ia]);
        xb[t] = __ldcs(&x[(long long)t * stride + ib]);
    }

    const float a1 = sigmoidf_(__ldg(alpha1)) - 0.5f;
    const float b1 = sigmoidf_(__ldg(beta1))  - 0.5f;
    const float a2 = sigmoidf_(__ldg(alpha2)) + 0.5f;
    const float b2 = sigmoidf_(__ldg(beta2))  + 0.5f;

    float4 vda = make_float4(0.f, 0.f, 0.f, 0.f);
    float4 vsa = make_float4(0.5f, 0.5f, 0.5f, 0.5f);
    float4 vdb = vda;
    float4 vsb = vsa;

    float4 oa[T_STEPS], ob[T_STEPS];

    #pragma unroll
    for (int t = 0; t < T_STEPS; t++) {
        step4(vda, vsa, xa[t], a1, b1, a2, b2, oa[t]);
        step4(vdb, vsb, xb[t], a1, b1, a2, b2, ob[t]);
    }

    // ---- Back-batched stores: 8 STG.128 ----
    #pragma unroll
    for (int t = 0; t < T_STEPS; t++) {
        __stcs(&out[(long long)t * stride + ia], oa[t]);
        __stcs(&out[(long long)t * stride + ib], ob[t]);
    }
}

extern "C" void kernel_launch(void* const* d_in, const int* in_sizes, int n_in,
                              void* d_out, int out_size)
{
    const float* x      = (const float*)d_in[0];
    const float* alpha1 = (const float*)d_in[1];
    const float* beta1  = (const float*)d_in[2];
    const float* alpha2 = (const float*)d_in[3];
    const float* beta2  = (const float*)d_in[4];
    float* out = (float*)d_out;

    const int n_total = in_sizes[0];          // 512*128*32*32 = 67,108,864
    const int n_slab  = n_total / T_STEPS;    // 16,777,216 elements per slab
    const int n4      = n_slab / 4;           // 4,194,304 float4 per slab

    const int block = 256;
    const int grid  = n4 / (block * 2);       // 8192 (exact: n4 = 2^22)

    online_neuron_kernel<<<grid, block>>>(
        (const float4*)x, alpha1, beta1, alpha2, beta2, (float4*)out, n4);
}